// round 15
// baseline (speedup 1.0000x reference)
#include <cuda_runtime.h>
#include <math.h>

#define S_LEN 2048
#define BATCH 64
#define INSZ  512
#define HID   512
#define BH    (BATCH * HID)          // 32768
#define GATES 1024                   // compact z|n gates
#define M_TOT (S_LEN * BATCH)        // 131072

#define NGROUP 8                     // independent batch groups
#define GSIZE  16                    // CTAs per group (j-slices)
#define BPG    8                     // batch rows per group
#define JPC    32                    // hidden units per CTA
#define GTHR   512                   // threads per gru CTA (16 warps)

// 512 MB scratch for x-projection (z|n gates, bias folded in)
__device__ float g_xp[(size_t)M_TOT * GATES];
// Per-(group, producer-CTA) monotonic publish flags + per-group done counter.
// Zero-init at load; reset by per-group tail handshake each run.
__device__ unsigned g_flag[NGROUP][GSIZE];
__device__ unsigned g_done[NGROUP];

// ---------------- packed fp32x2 helpers (B300 FFMA2 pipe) ----------------
__device__ __forceinline__ void fma2(unsigned long long& d,
                                     unsigned long long a,
                                     unsigned long long b) {
    asm("fma.rn.f32x2 %0, %1, %2, %0;" : "+l"(d) : "l"(a), "l"(b));
}
__device__ __forceinline__ unsigned long long dup2(float x) {
    unsigned long long r;
    asm("mov.b64 %0, {%1, %1};" : "=l"(r) : "f"(x));
    return r;
}
__device__ __forceinline__ float2 unpack2(unsigned long long v) {
    float2 f;
    asm("mov.b64 {%0, %1}, %2;" : "=f"(f.x), "=f"(f.y) : "l"(v));
    return f;
}
// ---------------- acquire/release sync (no L1-flushing fences) -----------
__device__ __forceinline__ unsigned atom_add_acqrel(unsigned* p, unsigned v) {
    unsigned r;
    asm volatile("atom.acq_rel.gpu.add.u32 %0, [%1], %2;"
                 : "=r"(r) : "l"(p), "r"(v) : "memory");
    return r;
}
__device__ __forceinline__ unsigned ld_acq(unsigned* p) {
    unsigned r;
    asm volatile("ld.acquire.gpu.u32 %0, [%1];" : "=r"(r) : "l"(p) : "memory");
    return r;
}
__device__ __forceinline__ void st_rel(unsigned* p, unsigned v) {
    asm volatile("st.release.gpu.u32 [%0], %1;" :: "l"(p), "r"(v) : "memory");
}

// ---------------------------------------------------------------------------
// Phase 1: C[m][n] = sum_k x[m][k] * Wih[HID + n][k] + bias[HID + n]
// 128x128x8 tiled SGEMM, ping-pong smem (ONE sync/iter), LDG prefetch hidden
// under the FFMA2 block. 256 threads, 8x8 micro-tile.
// ---------------------------------------------------------------------------
__global__ __launch_bounds__(256, 2) void xproj_kernel(
    const float* __restrict__ A,     // x  [M_TOT, INSZ]
    const float* __restrict__ Wih,   // [3H, INSZ]
    const float* __restrict__ bias)  // [3H]
{
    __shared__ float As[2][8][128];
    __shared__ float Bs[2][8][128];

    const int bx  = blockIdx.x;      // n tile (8)
    const int by  = blockIdx.y;      // m tile (1024)
    const int tid = threadIdx.x;

    const int lrow = tid >> 1;           // 0..127
    const int lcol = (tid & 1) * 4;      // 0 or 4

    const float* Aptr = A   + (size_t)(by * 128 + lrow) * INSZ + lcol;
    const float* Wptr = Wih + (size_t)(HID + bx * 128 + lrow) * INSZ + lcol;

    const int ty = tid >> 4;   // 0..15 (m)
    const int tx = tid & 15;   // 0..15 (n)

    unsigned long long acc[8][4];
#pragma unroll
    for (int i = 0; i < 8; i++)
#pragma unroll
        for (int j = 0; j < 4; j++) acc[i][j] = 0ULL;

    {
        float4 av = *(const float4*)(Aptr);
        float4 bv = *(const float4*)(Wptr);
        As[0][lcol + 0][lrow] = av.x; As[0][lcol + 1][lrow] = av.y;
        As[0][lcol + 2][lrow] = av.z; As[0][lcol + 3][lrow] = av.w;
        Bs[0][lcol + 0][lrow] = bv.x; Bs[0][lcol + 1][lrow] = bv.y;
        Bs[0][lcol + 2][lrow] = bv.z; Bs[0][lcol + 3][lrow] = bv.w;
    }
    __syncthreads();

    for (int k0 = 0; k0 < INSZ; k0 += 8) {
        const int p = (k0 >> 3) & 1;
        float4 av, bv;
        const bool more = (k0 + 8 < INSZ);
        if (more) {
            av = *(const float4*)(Aptr + k0 + 8);
            bv = *(const float4*)(Wptr + k0 + 8);
        }

#pragma unroll
        for (int k = 0; k < 8; k++) {
            float4 a0 = *(const float4*)&As[p][k][ty * 8];
            float4 a1 = *(const float4*)&As[p][k][ty * 8 + 4];
            ulonglong2 b0 = *(const ulonglong2*)&Bs[p][k][tx * 8];
            ulonglong2 b1 = *(const ulonglong2*)&Bs[p][k][tx * 8 + 4];
            float ar[8] = {a0.x, a0.y, a0.z, a0.w, a1.x, a1.y, a1.z, a1.w};
#pragma unroll
            for (int i = 0; i < 8; i++) {
                unsigned long long ad = dup2(ar[i]);
                fma2(acc[i][0], ad, b0.x);
                fma2(acc[i][1], ad, b0.y);
                fma2(acc[i][2], ad, b1.x);
                fma2(acc[i][3], ad, b1.y);
            }
        }

        if (more) {
            const int q = 1 - p;
            As[q][lcol + 0][lrow] = av.x; As[q][lcol + 1][lrow] = av.y;
            As[q][lcol + 2][lrow] = av.z; As[q][lcol + 3][lrow] = av.w;
            Bs[q][lcol + 0][lrow] = bv.x; Bs[q][lcol + 1][lrow] = bv.y;
            Bs[q][lcol + 2][lrow] = bv.z; Bs[q][lcol + 3][lrow] = bv.w;
        }
        __syncthreads();
    }

    const int n0 = bx * 128 + tx * 8;
    float bvs[8];
#pragma unroll
    for (int j = 0; j < 8; j++) bvs[j] = bias[HID + n0 + j];

    float* Cpt = g_xp + (size_t)(by * 128 + ty * 8) * GATES + n0;
#pragma unroll
    for (int i = 0; i < 8; i++) {
        float2 p0 = unpack2(acc[i][0]);
        float2 p1 = unpack2(acc[i][1]);
        float2 p2 = unpack2(acc[i][2]);
        float2 p3 = unpack2(acc[i][3]);
        float4 o0, o1;
        o0.x = p0.x + bvs[0]; o0.y = p0.y + bvs[1];
        o0.z = p1.x + bvs[2]; o0.w = p1.y + bvs[3];
        o1.x = p2.x + bvs[4]; o1.y = p2.y + bvs[5];
        o1.z = p3.x + bvs[6]; o1.w = p3.y + bvs[7];
        *(float4*)(Cpt + (size_t)i * GATES)     = o0;
        *(float4*)(Cpt + (size_t)i * GATES + 4) = o1;
    }
}

// ---------------------------------------------------------------------------
// Phase 2: batch-grouped recurrence with FINE-GRAINED slice flags.
// 128 CTAs x 512 threads = 8 groups x 16 j-slices. Thread (lane=j, warp=ks)
// holds both gate-row slices (k in [ks*32, ks*32+32)) in 32 packed regs.
// The dot's k-slice ks equals producer CTA ks's j-slice of h, so the group
// barrier is replaced by 16 producer->consumer edges: producer CTA publishes
// its h slice to out, then tid0 st.release's g_flag[grp][rank] = t+1; at
// step t, warp ks spins ld.acquire g_flag[grp][ks] >= t, LDGs its 1 KB
// slice, stages to warp-private smem, and dots. No CTA ever waits for the
// slowest-of-16; waits overlap compute of other warps.
// ---------------------------------------------------------------------------
__global__ __launch_bounds__(GTHR) void gru_kernel(
    const float* __restrict__ Whh,   // [3H, HID]
    float* __restrict__ out)         // [S*BH + BH]
{
    __shared__ float h_w[16 * 256];              // per-warp h slice [warp][b][32]
    __shared__ float part[16 * BPG * JPC * 2];   // [warp][b][j][{z,n}] 32 KB

    const int tid   = threadIdx.x;
    const int lane  = tid & 31;          // j within CTA
    const int warp  = tid >> 5;          // 0..15 = k-slice = producer rank
    const int grp   = blockIdx.x >> 4;   // 0..7
    const int rank  = blockIdx.x & 15;   // j-slice of this CTA
    const int jbase = rank * JPC;
    // Owner cell (epilogue): threads 0..255 own (ob, oj)
    const int ob  = tid >> 5;            // 0..7 (valid when tid < 256)
    const int oj  = tid & 31;
    const int b_g = grp * BPG + ob;
    const int j_g = jbase + oj;

    // ---- Load this thread's z and n weight slices into registers (once) ----
    unsigned long long wz[16], wn[16];
    {
        const float* zrow = Whh + (size_t)(HID     + jbase + lane) * HID + warp * 32;
        const float* nrow = Whh + (size_t)(2 * HID + jbase + lane) * HID + warp * 32;
#pragma unroll
        for (int i = 0; i < 8; i++) {
            ulonglong2 vz = *(const ulonglong2*)(zrow + i * 4);
            wz[2 * i]     = vz.x;
            wz[2 * i + 1] = vz.y;
        }
#pragma unroll
        for (int i = 0; i < 8; i++) {
            ulonglong2 vn = *(const ulonglong2*)(nrow + i * 4);
            wn[2 * i]     = vn.x;
            wn[2 * i + 1] = vn.y;
        }
    }

    unsigned* myflag   = &g_flag[grp][rank];     // we produce this
    unsigned* srcflag  = &g_flag[grp][warp];     // our warp consumes this
    float*    mypart   = part + warp * 512;      // [b][j][{z,n}] for this warp
    float*    myslice  = h_w + warp * 256;

    float hold = 0.f;                    // h_{t-1}(b_g, j_g), owners only

    for (int t = 0; t < S_LEN; t++) {
        // xp prefetch for the owned cell (independent of h)
        float xpz = 0.f, xpn = 0.f;
        if (tid < 256) {
            const float* xprow = g_xp + ((size_t)t * BATCH + b_g) * GATES;
            xpz = xprow[j_g];
            xpn = xprow[HID + j_g];
        }

        float sz = 0.f, sn = 0.f;
        if (t > 0) {
            // Wait for producer CTA `warp` to publish h_{t-1} slice (flag >= t).
            while (ld_acq(srcflag) < (unsigned)t) {}

            // Stage the 256-float slice: 2 float4 per lane, coalesced.
            const float* src = out + (size_t)(t - 1) * BH
                             + (size_t)(grp * BPG) * HID + warp * 32;
#pragma unroll
            for (int r = 0; r < 2; r++) {
                int fi = lane + r * 32;          // float4 index 0..63
                int bb = fi >> 3, off = (fi & 7) << 2;
                *(float4*)(myslice + bb * 32 + off) =
                    *(const float4*)(src + (size_t)bb * HID + off);
            }
            __syncwarp();

            // Dot: 32-k packed dot (both gates) vs register weights, 8 b.
#pragma unroll 2
            for (int b = 0; b < 8; b++) {
                const float* hp = myslice + b * 32;
                unsigned long long az0 = 0ULL, az1 = 0ULL;
                unsigned long long an0 = 0ULL, an1 = 0ULL;
#pragma unroll
                for (int c = 0; c < 8; c++) {
                    ulonglong2 h2 = *(const ulonglong2*)(hp + c * 4);
                    fma2(az0, h2.x, wz[2 * c]);
                    fma2(az1, h2.y, wz[2 * c + 1]);
                    fma2(an0, h2.x, wn[2 * c]);
                    fma2(an1, h2.y, wn[2 * c + 1]);
                }
                float2 ez0 = unpack2(az0), ez1 = unpack2(az1);
                float2 en0 = unpack2(an0), en1 = unpack2(an1);
                float2 v = make_float2((ez0.x + ez0.y) + (ez1.x + ez1.y),
                                       (en0.x + en0.y) + (en1.x + en1.y));
                *(float2*)(mypart + (b * 32 + lane) * 2) = v;
            }
            __syncthreads();

            // Owners reduce the 16 k-slice partials (float2 = both gates).
            if (tid < 256) {
                const float* pp = part + (ob * 32 + oj) * 2;
                float sza = 0.f, szb = 0.f, sna = 0.f, snb = 0.f;
#pragma unroll
                for (int s = 0; s < 16; s += 2) {
                    float2 p0 = *(const float2*)(pp + s * 512);
                    float2 p1 = *(const float2*)(pp + (s + 1) * 512);
                    sza += p0.x; sna += p0.y;
                    szb += p1.x; snb += p1.y;
                }
                sz = sza + szb;
                sn = sna + snb;
            }
        }

        if (tid < 256) {
            // Gates + state update (thread owns (b_g, j_g); hold in register).
            float gz = sz + xpz;
            float gn = sn + xpn;
            float z  = 1.f / (1.f + __expf(-gz));
            float e  = __expf(-2.f * fabsf(gn));        // in (0,1]
            float tt = (1.f - e) / (1.f + e);
            float n  = copysignf(tt, gn);
            float hn = (1.f - z) * n + z * hold;
            hold = hn;

            out[(size_t)t * BH + (size_t)b_g * HID + j_g] = hn;
            if (t == S_LEN - 1)
                out[(size_t)S_LEN * BH + (size_t)b_g * HID + j_g] = hn;
        }

        // Order owner STGs before the flag release (R13-validated pattern).
        __syncthreads();
        if (t < S_LEN - 1 && tid == 0)
            st_rel(myflag, (unsigned)(t + 1));
    }

    // Per-group tail handshake: last CTA resets flags for the next replay.
    // All CTAs of the group are past their final consume when they arrive.
    if (tid == 0) {
        unsigned old = atom_add_acqrel(&g_done[grp], 1u);
        if (old == GSIZE - 1u) {
#pragma unroll
            for (int r = 0; r < GSIZE; r++)
                st_rel(&g_flag[grp][r], 0u);
            st_rel(&g_done[grp], 0u);
        }
    }
}

extern "C" void kernel_launch(void* const* d_in, const int* in_sizes, int n_in,
                              void* d_out, int out_size) {
    const float* x    = (const float*)d_in[0];
    const float* wih  = (const float*)d_in[1];
    const float* whh  = (const float*)d_in[2];
    const float* bias = (const float*)d_in[3];
    float* out = (float*)d_out;

    dim3 grid1(GATES / 128, M_TOT / 128);
    xproj_kernel<<<grid1, 256>>>(x, wih, bias);

    gru_kernel<<<NGROUP * GSIZE, GTHR>>>(whh, out);
}

// round 16
// speedup vs baseline: 1.7171x; 1.7171x over previous
#include <cuda_runtime.h>
#include <math.h>

#define S_LEN 2048
#define BATCH 64
#define INSZ  512
#define HID   512
#define BH    (BATCH * HID)          // 32768
#define GATES 1024                   // compact z|n gates
#define M_TOT (S_LEN * BATCH)        // 131072

#define NGROUP 8                     // clusters (batch groups)
#define CLSZ   16                    // CTAs per cluster (j-slices)
#define BPG    8                     // batch rows per group
#define JPC    32                    // hidden units per CTA
#define GTHR   512                   // threads per gru CTA (16 warps)

// 512 MB scratch for x-projection (z|n gates, bias folded in)
__device__ float g_xp[(size_t)M_TOT * GATES];

// ---------------- packed fp32x2 helpers (B300 FFMA2 pipe) ----------------
__device__ __forceinline__ void fma2(unsigned long long& d,
                                     unsigned long long a,
                                     unsigned long long b) {
    asm("fma.rn.f32x2 %0, %1, %2, %0;" : "+l"(d) : "l"(a), "l"(b));
}
__device__ __forceinline__ unsigned long long dup2(float x) {
    unsigned long long r;
    asm("mov.b64 %0, {%1, %1};" : "=l"(r) : "f"(x));
    return r;
}
__device__ __forceinline__ float2 unpack2(unsigned long long v) {
    float2 f;
    asm("mov.b64 {%0, %1}, %2;" : "=f"(f.x), "=f"(f.y) : "l"(v));
    return f;
}
// ---------------- cluster / DSMEM helpers --------------------------------
__device__ __forceinline__ unsigned smem_u32(const void* p) {
    unsigned a;
    asm("{ .reg .u64 t; cvta.to.shared.u64 t, %1; cvt.u32.u64 %0, t; }"
        : "=r"(a) : "l"(p));
    return a;
}
__device__ __forceinline__ unsigned mapa_u32(unsigned addr, unsigned rank) {
    unsigned r;
    asm("mapa.shared::cluster.u32 %0, %1, %2;" : "=r"(r) : "r"(addr), "r"(rank));
    return r;
}
__device__ __forceinline__ void st_dsmem_b32(unsigned addr, unsigned v) {
    asm volatile("st.shared::cluster.b32 [%0], %1;" :: "r"(addr), "r"(v) : "memory");
}
#define CLUSTER_ARRIVE() asm volatile("barrier.cluster.arrive.aligned;" ::: "memory")
#define CLUSTER_WAIT()   asm volatile("barrier.cluster.wait.aligned;"   ::: "memory")

// ---------------------------------------------------------------------------
// Phase 1: C[m][n] = sum_k x[m][k] * Wih[HID + n][k] + bias[HID + n]
// 128x128x8 tiled SGEMM, ping-pong smem (ONE sync/iter), LDG prefetch hidden
// under the FFMA2 block. 256 threads, 8x8 micro-tile.
// ---------------------------------------------------------------------------
__global__ __launch_bounds__(256, 2) void xproj_kernel(
    const float* __restrict__ A,     // x  [M_TOT, INSZ]
    const float* __restrict__ Wih,   // [3H, INSZ]
    const float* __restrict__ bias)  // [3H]
{
    __shared__ float As[2][8][128];
    __shared__ float Bs[2][8][128];

    const int bx  = blockIdx.x;      // n tile (8)
    const int by  = blockIdx.y;      // m tile (1024)
    const int tid = threadIdx.x;

    const int lrow = tid >> 1;           // 0..127
    const int lcol = (tid & 1) * 4;      // 0 or 4

    const float* Aptr = A   + (size_t)(by * 128 + lrow) * INSZ + lcol;
    const float* Wptr = Wih + (size_t)(HID + bx * 128 + lrow) * INSZ + lcol;

    const int ty = tid >> 4;   // 0..15 (m)
    const int tx = tid & 15;   // 0..15 (n)

    unsigned long long acc[8][4];
#pragma unroll
    for (int i = 0; i < 8; i++)
#pragma unroll
        for (int j = 0; j < 4; j++) acc[i][j] = 0ULL;

    {
        float4 av = *(const float4*)(Aptr);
        float4 bv = *(const float4*)(Wptr);
        As[0][lcol + 0][lrow] = av.x; As[0][lcol + 1][lrow] = av.y;
        As[0][lcol + 2][lrow] = av.z; As[0][lcol + 3][lrow] = av.w;
        Bs[0][lcol + 0][lrow] = bv.x; Bs[0][lcol + 1][lrow] = bv.y;
        Bs[0][lcol + 2][lrow] = bv.z; Bs[0][lcol + 3][lrow] = bv.w;
    }
    __syncthreads();

    for (int k0 = 0; k0 < INSZ; k0 += 8) {
        const int p = (k0 >> 3) & 1;
        float4 av, bv;
        const bool more = (k0 + 8 < INSZ);
        if (more) {
            av = *(const float4*)(Aptr + k0 + 8);
            bv = *(const float4*)(Wptr + k0 + 8);
        }

#pragma unroll
        for (int k = 0; k < 8; k++) {
            float4 a0 = *(const float4*)&As[p][k][ty * 8];
            float4 a1 = *(const float4*)&As[p][k][ty * 8 + 4];
            ulonglong2 b0 = *(const ulonglong2*)&Bs[p][k][tx * 8];
            ulonglong2 b1 = *(const ulonglong2*)&Bs[p][k][tx * 8 + 4];
            float ar[8] = {a0.x, a0.y, a0.z, a0.w, a1.x, a1.y, a1.z, a1.w};
#pragma unroll
            for (int i = 0; i < 8; i++) {
                unsigned long long ad = dup2(ar[i]);
                fma2(acc[i][0], ad, b0.x);
                fma2(acc[i][1], ad, b0.y);
                fma2(acc[i][2], ad, b1.x);
                fma2(acc[i][3], ad, b1.y);
            }
        }

        if (more) {
            const int q = 1 - p;
            As[q][lcol + 0][lrow] = av.x; As[q][lcol + 1][lrow] = av.y;
            As[q][lcol + 2][lrow] = av.z; As[q][lcol + 3][lrow] = av.w;
            Bs[q][lcol + 0][lrow] = bv.x; Bs[q][lcol + 1][lrow] = bv.y;
            Bs[q][lcol + 2][lrow] = bv.z; Bs[q][lcol + 3][lrow] = bv.w;
        }
        __syncthreads();
    }

    const int n0 = bx * 128 + tx * 8;
    float bvs[8];
#pragma unroll
    for (int j = 0; j < 8; j++) bvs[j] = bias[HID + n0 + j];

    float* Cpt = g_xp + (size_t)(by * 128 + ty * 8) * GATES + n0;
#pragma unroll
    for (int i = 0; i < 8; i++) {
        float2 p0 = unpack2(acc[i][0]);
        float2 p1 = unpack2(acc[i][1]);
        float2 p2 = unpack2(acc[i][2]);
        float2 p3 = unpack2(acc[i][3]);
        float4 o0, o1;
        o0.x = p0.x + bvs[0]; o0.y = p0.y + bvs[1];
        o0.z = p1.x + bvs[2]; o0.w = p1.y + bvs[3];
        o1.x = p2.x + bvs[4]; o1.y = p2.y + bvs[5];
        o1.z = p3.x + bvs[6]; o1.w = p3.y + bvs[7];
        *(float4*)(Cpt + (size_t)i * GATES)     = o0;
        *(float4*)(Cpt + (size_t)i * GATES + 4) = o1;
    }
}

// ---------------------------------------------------------------------------
// Phase 2: cluster recurrence with PRODUCER-PUSH DSMEM h-exchange.
// 8 clusters x 16 CTAs x 512 threads. CTA rank r owns j in [32r, 32r+32),
// both gate rows in registers (R13 layout: warp = 32-k slice, lane = j).
// Each step: owners compute h(b,j) and PUSH it into every peer's smem parity
// buffer (fire-and-forget st.shared::cluster — no remote-load latency, the
// R14 mistake), then one barrier.cluster.arrive/.wait per step. The dot reads
// LOCAL smem (29-cyc LDS broadcast), identical to R13's fast path, but the
// whole STG->atomic->sense->poll->LDG restage chain is gone. Parity-2 buffer
// + one barrier/step is race-free: writes at t+1 hit parity (t-1)&1, and
// wait(t+1) requires all peers' arrive(t), which follows their reads of it.
// No global sync state at all -> trivially graph-replay deterministic.
// ---------------------------------------------------------------------------
extern __shared__ float gsm[];

__global__ __launch_bounds__(GTHR) __cluster_dims__(CLSZ, 1, 1)
void gru_kernel(
    const float* __restrict__ Whh,   // [3H, HID]
    float* __restrict__ out)         // [S*BH + BH]
{
    float* hbuf = gsm;                     // [2][BPG][HID]  32 KB
    float* part = gsm + 2 * BPG * HID;     // [16][BPG][JPC][{z,n}] 32 KB

    const int tid   = threadIdx.x;
    const int lane  = tid & 31;          // j within CTA
    const int warp  = tid >> 5;          // 0..15 = 32-k slice
    const int rank  = blockIdx.x & 15;   // j-slice of this CTA
    const int grp   = blockIdx.x >> 4;   // 0..7 (cluster id)
    const int jbase = rank * JPC;
    // Owner cell (epilogue): threads 0..255 own (ob, oj)
    const int ob  = tid >> 5;            // 0..7 (valid when tid < 256)
    const int oj  = tid & 31;
    const int b_g = grp * BPG + ob;
    const int j_g = jbase + oj;          // == h-vector index rank*32+oj

    // ---- Load this thread's z and n weight slices into registers (once) ----
    unsigned long long wz[16], wn[16];
    {
        const float* zrow = Whh + (size_t)(HID     + jbase + lane) * HID + warp * 32;
        const float* nrow = Whh + (size_t)(2 * HID + jbase + lane) * HID + warp * 32;
#pragma unroll
        for (int i = 0; i < 8; i++) {
            ulonglong2 vz = *(const ulonglong2*)(zrow + i * 4);
            wz[2 * i]     = vz.x;
            wz[2 * i + 1] = vz.y;
        }
#pragma unroll
        for (int i = 0; i < 8; i++) {
            ulonglong2 vn = *(const ulonglong2*)(nrow + i * 4);
            wn[2 * i]     = vn.x;
            wn[2 * i + 1] = vn.y;
        }
    }

    // Peer smem base addresses of hbuf (mapa once; add offsets per step).
    const unsigned hb_local = smem_u32(hbuf);
    unsigned peer[CLSZ];
#pragma unroll
    for (int p = 0; p < CLSZ; p++) peer[p] = mapa_u32(hb_local, (unsigned)p);

    float hold = 0.f;                    // h_{t-1}(b_g, j_g), owners only

    for (int t = 0; t < S_LEN; t++) {
        // xp prefetch for the owned cell — issued BEFORE the cluster wait.
        float xpz = 0.f, xpn = 0.f;
        if (tid < 256) {
            const float* xprow = g_xp + ((size_t)t * BATCH + b_g) * GATES;
            xpz = xprow[j_g];
            xpn = xprow[HID + j_g];
        }

        float sz = 0.f, sn = 0.f;
        if (t > 0) {
            CLUSTER_WAIT();              // acquire: all peers' h_{t-1} landed

            // Dot from LOCAL smem, parity (t-1)&1. Warp-uniform addresses.
            const float* hpw = hbuf + ((t - 1) & 1) * (BPG * HID) + warp * 32;
#pragma unroll 2
            for (int b = 0; b < 8; b++) {
                const float* hp = hpw + b * HID;
                unsigned long long az0 = 0ULL, az1 = 0ULL;
                unsigned long long an0 = 0ULL, an1 = 0ULL;
#pragma unroll
                for (int c = 0; c < 8; c++) {
                    ulonglong2 h2 = *(const ulonglong2*)(hp + c * 4);
                    fma2(az0, h2.x, wz[2 * c]);
                    fma2(az1, h2.y, wz[2 * c + 1]);
                    fma2(an0, h2.x, wn[2 * c]);
                    fma2(an1, h2.y, wn[2 * c + 1]);
                }
                float2 ez0 = unpack2(az0), ez1 = unpack2(az1);
                float2 en0 = unpack2(an0), en1 = unpack2(an1);
                float2 v = make_float2((ez0.x + ez0.y) + (ez1.x + ez1.y),
                                       (en0.x + en0.y) + (en1.x + en1.y));
                *(float2*)(part + (warp * 256 + b * 32 + lane) * 2) = v;
            }
            __syncthreads();

            // Owners reduce the 16 k-slice partials (float2 = both gates).
            if (tid < 256) {
                const float* pp = part + (ob * 32 + oj) * 2;
                float sza = 0.f, szb = 0.f, sna = 0.f, snb = 0.f;
#pragma unroll
                for (int s = 0; s < 16; s += 2) {
                    float2 p0 = *(const float2*)(pp + s * 512);
                    float2 p1 = *(const float2*)(pp + (s + 1) * 512);
                    sza += p0.x; sna += p0.y;
                    szb += p1.x; snb += p1.y;
                }
                sz = sza + szb;
                sn = sna + snb;
            }
        }

        if (tid < 256) {
            // Gates + state update (thread owns (b_g, j_g); hold in register).
            float gz = sz + xpz;
            float gn = sn + xpn;
            float z  = 1.f / (1.f + __expf(-gz));
            float e  = __expf(-2.f * fabsf(gn));        // in (0,1]
            float tt = (1.f - e) / (1.f + e);
            float n  = copysignf(tt, gn);
            float hn = (1.f - z) * n + z * hold;
            hold = hn;

            // Push h(b,j) into every peer's parity buffer (incl. self).
            const unsigned off = (unsigned)((((t & 1) * BPG + ob) * HID + j_g) * 4);
            const unsigned hv  = __float_as_uint(hn);
#pragma unroll
            for (int p = 0; p < CLSZ; p++)
                st_dsmem_b32(peer[p] + off, hv);

            out[(size_t)t * BH + (size_t)b_g * HID + j_g] = hn;
            if (t == S_LEN - 1)
                out[(size_t)S_LEN * BH + (size_t)b_g * HID + j_g] = hn;
        }

        CLUSTER_ARRIVE();                // release: pushes visible after wait
    }

    CLUSTER_WAIT();                      // nobody exits while peers still read
}

extern "C" void kernel_launch(void* const* d_in, const int* in_sizes, int n_in,
                              void* d_out, int out_size) {
    const float* x    = (const float*)d_in[0];
    const float* wih  = (const float*)d_in[1];
    const float* whh  = (const float*)d_in[2];
    const float* bias = (const float*)d_in[3];
    float* out = (float*)d_out;

    const size_t smem_bytes = (2 * BPG * HID + 16 * BPG * JPC * 2) * sizeof(float);

    static int configured = 0;
    if (!configured) {
        cudaFuncSetAttribute(gru_kernel,
                             cudaFuncAttributeNonPortableClusterSizeAllowed, 1);
        cudaFuncSetAttribute(gru_kernel,
                             cudaFuncAttributeMaxDynamicSharedMemorySize,
                             (int)smem_bytes);
        configured = 1;
    }

    dim3 grid1(GATES / 128, M_TOT / 128);
    xproj_kernel<<<grid1, 256>>>(x, wih, bias);

    gru_kernel<<<NGROUP * CLSZ, GTHR, smem_bytes>>>(whh, out);
}

// round 17
// speedup vs baseline: 2.3004x; 1.3397x over previous
#include <cuda_runtime.h>
#include <math.h>

#define S_LEN 2048
#define BATCH 64
#define INSZ  512
#define HID   512
#define BH    (BATCH * HID)          // 32768
#define GATES 1024                   // compact z|n gates
#define M_TOT (S_LEN * BATCH)        // 131072

#define NGROUP 8                     // independent batch groups
#define GSIZE  16                    // CTAs per group (j-slices)
#define BPG    8                     // batch rows per group
#define JPC    32                    // hidden units per CTA
#define HSTR   516                   // per-b h stride in floats
#define THR    640                   // 512 gru threads + 128 xproj threads
#define NWIN   128                   // xp windows (16 timesteps each)

// xp scratch (z|n gates, bias folded in) — produced and consumed per-CTA
__device__ float g_xp[(size_t)M_TOT * GATES];
// Per-group barrier state (zero-init; reset by per-group tail handshake)
__device__ unsigned g_cnt[NGROUP];
__device__ unsigned g_sense[NGROUP];
__device__ unsigned g_done[NGROUP];

// ---------------- packed fp32x2 helpers (B300 FFMA2 pipe) ----------------
__device__ __forceinline__ void fma2(unsigned long long& d,
                                     unsigned long long a,
                                     unsigned long long b) {
    asm("fma.rn.f32x2 %0, %1, %2, %0;" : "+l"(d) : "l"(a), "l"(b));
}
__device__ __forceinline__ unsigned long long dup2(float x) {
    unsigned long long r;
    asm("mov.b64 %0, {%1, %1};" : "=l"(r) : "f"(x));
    return r;
}
__device__ __forceinline__ float2 unpack2(unsigned long long v) {
    float2 f;
    asm("mov.b64 {%0, %1}, %2;" : "=f"(f.x), "=f"(f.y) : "l"(v));
    return f;
}
// ---------------- sync helpers -------------------------------------------
__device__ __forceinline__ unsigned atom_add_acqrel(unsigned* p, unsigned v) {
    unsigned r;
    asm volatile("atom.acq_rel.gpu.add.u32 %0, [%1], %2;"
                 : "=r"(r) : "l"(p), "r"(v) : "memory");
    return r;
}
__device__ __forceinline__ unsigned ld_acq(unsigned* p) {
    unsigned r;
    asm volatile("ld.acquire.gpu.u32 %0, [%1];" : "=r"(r) : "l"(p) : "memory");
    return r;
}
__device__ __forceinline__ void st_rel(unsigned* p, unsigned v) {
    asm volatile("st.release.gpu.u32 [%0], %1;" :: "l"(p), "r"(v) : "memory");
}
__device__ __forceinline__ unsigned smem_u32(const void* p) {
    unsigned a;
    asm("{ .reg .u64 t; cvta.to.shared.u64 t, %1; cvt.u32.u64 %0, t; }"
        : "=r"(a) : "l"(p));
    return a;
}
__device__ __forceinline__ void st_rel_cta_sh(unsigned addr, unsigned v) {
    asm volatile("st.release.cta.shared.u32 [%0], %1;" :: "r"(addr), "r"(v) : "memory");
}
__device__ __forceinline__ unsigned ld_acq_cta_sh(unsigned addr) {
    unsigned r;
    asm volatile("ld.acquire.cta.shared.u32 %0, [%1];" : "=r"(r) : "r"(addr) : "memory");
    return r;
}
#define BAR_GRU() asm volatile("bar.sync 1, 512;" ::: "memory")
#define BAR_XP()  asm volatile("bar.sync 2, 128;" ::: "memory")

// Dynamic smem layout (float offsets)
#define OFF_H    0                         // [BPG][HSTR]           4128
#define OFF_PART 4128                      // [16][256][2]          8192
#define OFF_WIH  12320                     // [512][68]            34816
#define OFF_XS   47136                     // [8][132]              1056
#define OFF_FLAG 48200                     // 1 unsigned (aligned)
#define SM_FLOATS 48256

extern __shared__ float sm[];

// ---------------------------------------------------------------------------
// Fused kernel: 128 CTAs x 640 threads = 8 groups x 16 j-slices.
// Warps 0-15 (512 thr): R13 recurrence — weights-in-registers dot, smem part
//   reduce, owner gates, inter-CTA acq_rel h-exchange via out + g_cnt/g_sense.
// Warps 16-19 (128 thr): xp producers — GEMM over 128-row windows (16 t x
//   8 b) x this CTA's 64 gate cols, Wih tile smem-resident, results to g_xp,
//   window-done flag in smem (st.release.cta). xp never crosses CTAs.
// ---------------------------------------------------------------------------
__global__ __launch_bounds__(THR, 1) void gru_fused(
    const float* __restrict__ x,     // [M_TOT, INSZ]
    const float* __restrict__ Wih,   // [3H, INSZ]
    const float* __restrict__ Whh,   // [3H, HID]
    const float* __restrict__ bias,  // [3H]
    float* __restrict__ out)         // [S*BH + BH]
{
    float* h_s    = sm + OFF_H;
    float* part   = sm + OFF_PART;
    float* wih_s  = sm + OFF_WIH;    // [k][68] transposed, rows 0..63 = z|n
    float* xs     = sm + OFF_XS;     // [8][132] x k-chunk, [k][m]
    const unsigned flag_a = smem_u32(sm + OFF_FLAG);

    const int tid   = threadIdx.x;
    const int grp   = blockIdx.x >> 4;
    const int rank  = blockIdx.x & 15;
    const int jbase = rank * JPC;

    if (tid == 512) *(unsigned*)(sm + OFF_FLAG) = 0u;
    __syncthreads();                 // ONLY full-CTA sync; roles diverge after

    if (tid < 512) {
        // ==================== RECURRENCE ROLE (R13) ====================
        const int lane = tid & 31;
        const int warp = tid >> 5;           // 0..15 = 32-k slice
        const int ob   = tid >> 5;           // owner b (tid < 256)
        const int oj   = tid & 31;
        const int b_g  = grp * BPG + ob;
        const int j_g  = jbase + oj;

        unsigned long long wz[16], wn[16];
        {
            const float* zrow = Whh + (size_t)(HID     + jbase + lane) * HID + warp * 32;
            const float* nrow = Whh + (size_t)(2 * HID + jbase + lane) * HID + warp * 32;
#pragma unroll
            for (int i = 0; i < 8; i++) {
                ulonglong2 vz = *(const ulonglong2*)(zrow + i * 4);
                wz[2 * i] = vz.x; wz[2 * i + 1] = vz.y;
            }
#pragma unroll
            for (int i = 0; i < 8; i++) {
                ulonglong2 vn = *(const ulonglong2*)(nrow + i * 4);
                wn[2 * i] = vn.x; wn[2 * i + 1] = vn.y;
            }
        }

        unsigned* cntp   = &g_cnt[grp];
        unsigned* sensep = &g_sense[grp];
        float hold = 0.f;

        for (int t = 0; t < S_LEN; t++) {
            // Wait for our producers' xp window, then prefetch xp.
            float xpz = 0.f, xpn = 0.f;
            if (tid < 256) {
                const unsigned need = (unsigned)(t >> 4) + 1u;
                while (ld_acq_cta_sh(flag_a) < need) {}
                const float* xprow = g_xp + ((size_t)t * BATCH + b_g) * GATES;
                xpz = xprow[j_g];
                xpn = xprow[HID + j_g];
            }

            float sz = 0.f, sn = 0.f;
            if (t > 0) {
                const float* hsrc = out + (size_t)(t - 1) * BH + (size_t)grp * BPG * HID;
#pragma unroll
                for (int r = 0; r < 2; r++) {
                    int idx = tid + r * 512;
                    int bb = idx >> 7, k4 = (idx & 127) << 2;
                    *(float4*)(h_s + bb * HSTR + k4) =
                        *(const float4*)(hsrc + bb * HID + k4);
                }
                BAR_GRU();

                const float* hbase = h_s + warp * 32;
#pragma unroll 2
                for (int b = 0; b < 8; b++) {
                    const float* hp = hbase + b * HSTR;
                    unsigned long long az0 = 0ULL, az1 = 0ULL;
                    unsigned long long an0 = 0ULL, an1 = 0ULL;
#pragma unroll
                    for (int c = 0; c < 8; c++) {
                        ulonglong2 h2 = *(const ulonglong2*)(hp + c * 4);
                        fma2(az0, h2.x, wz[2 * c]);
                        fma2(az1, h2.y, wz[2 * c + 1]);
                        fma2(an0, h2.x, wn[2 * c]);
                        fma2(an1, h2.y, wn[2 * c + 1]);
                    }
                    float2 ez0 = unpack2(az0), ez1 = unpack2(az1);
                    float2 en0 = unpack2(an0), en1 = unpack2(an1);
                    float2 v = make_float2((ez0.x + ez0.y) + (ez1.x + ez1.y),
                                           (en0.x + en0.y) + (en1.x + en1.y));
                    *(float2*)(part + (warp * 256 + b * 32 + lane) * 2) = v;
                }
                BAR_GRU();

                if (tid < 256) {
                    const float* pp = part + (ob * 32 + oj) * 2;
                    float sza = 0.f, szb = 0.f, sna = 0.f, snb = 0.f;
#pragma unroll
                    for (int s = 0; s < 16; s += 2) {
                        float2 p0 = *(const float2*)(pp + s * 512);
                        float2 p1 = *(const float2*)(pp + (s + 1) * 512);
                        sza += p0.x; sna += p0.y;
                        szb += p1.x; snb += p1.y;
                    }
                    sz = sza + szb;
                    sn = sna + snb;
                }
            }

            if (tid < 256) {
                float gz = sz + xpz;
                float gn = sn + xpn;
                float z  = 1.f / (1.f + __expf(-gz));
                float e  = __expf(-2.f * fabsf(gn));
                float tt = (1.f - e) / (1.f + e);
                float n  = copysignf(tt, gn);
                float hn = (1.f - z) * n + z * hold;
                hold = hn;

                out[(size_t)t * BH + (size_t)b_g * HID + j_g] = hn;
                if (t == S_LEN - 1)
                    out[(size_t)S_LEN * BH + (size_t)b_g * HID + j_g] = hn;
            }

            BAR_GRU();                       // owner STGs issued
            if (t < S_LEN - 1) {
                if (tid == 0) {
                    unsigned target = (unsigned)(t + 1) * GSIZE;
                    unsigned old = atom_add_acqrel(cntp, 1u);
                    if (old == target - 1u) {
                        st_rel(sensep, (unsigned)(t + 1));
                    } else {
                        while (ld_acq(sensep) < (unsigned)(t + 1)) {}
                    }
                }
                BAR_GRU();
            }
        }

        if (tid == 0) {
            unsigned old = atom_add_acqrel(&g_done[grp], 1u);
            if (old == GSIZE - 1u) {
                st_rel(&g_cnt[grp], 0u);
                st_rel(&g_sense[grp], 0u);
                st_rel(&g_done[grp], 0u);
            }
        }
    } else {
        // ==================== XP PRODUCER ROLE ====================
        const int xid = tid - 512;           // 0..127
        const int tm  = xid >> 3;            // 0..15 = timestep within window
        const int tn  = xid & 7;             // 0..7  = n-octet (8 cols)

        // Stage Wih tile (64 gate rows of this CTA) transposed: wih_s[k][r].
        for (int i = xid; i < 64 * INSZ; i += 128) {
            int r = i >> 9, k = i & 511;
            int row = ((r < 32) ? HID + jbase + r : 2 * HID + jbase + (r - 32));
            wih_s[k * 68 + r] = Wih[(size_t)row * INSZ + k];
        }
        // Bias for this thread's 8 columns (n-octet tn).
        float bv[8];
#pragma unroll
        for (int j = 0; j < 8; j++) {
            int c = tn * 8 + j;
            int row = (c < 32) ? (HID + jbase + c) : (2 * HID + jbase + (c - 32));
            bv[j] = bias[row];
        }
        BAR_XP();

        for (int W = 0; W < NWIN; W++) {
            const int t_w = W * 16 + tm;     // this thread's timestep
            // x rows for loading: thread xid owns window row m = xid.
            const float* xrow = x + ((size_t)(W * 16 + (xid >> 3)) * BATCH
                                     + grp * BPG + (xid & 7)) * INSZ;

            unsigned long long acc[8][4];
#pragma unroll
            for (int i = 0; i < 8; i++)
#pragma unroll
                for (int j = 0; j < 4; j++) acc[i][j] = 0ULL;

            // Prefetch k-chunk 0.
            float4 p0 = *(const float4*)(xrow);
            float4 p1 = *(const float4*)(xrow + 4);

            for (int kc = 0; kc < INSZ; kc += 8) {
                // Scatter prefetched chunk to xs[k][m].
                xs[0 * 132 + xid] = p0.x; xs[1 * 132 + xid] = p0.y;
                xs[2 * 132 + xid] = p0.z; xs[3 * 132 + xid] = p0.w;
                xs[4 * 132 + xid] = p1.x; xs[5 * 132 + xid] = p1.y;
                xs[6 * 132 + xid] = p1.z; xs[7 * 132 + xid] = p1.w;
                BAR_XP();

                if (kc + 8 < INSZ) {
                    p0 = *(const float4*)(xrow + kc + 8);
                    p1 = *(const float4*)(xrow + kc + 12);
                }

#pragma unroll
                for (int k = 0; k < 8; k++) {
                    const float* ar = xs + k * 132 + tm * 8;
                    const float* br = wih_s + (size_t)(kc + k) * 68 + tn * 8;
                    ulonglong2 b0 = *(const ulonglong2*)(br);
                    ulonglong2 b1 = *(const ulonglong2*)(br + 4);
                    float a0 = ar[0], a1 = ar[1], a2 = ar[2], a3 = ar[3];
                    float a4 = ar[4], a5 = ar[5], a6 = ar[6], a7 = ar[7];
                    float av[8] = {a0, a1, a2, a3, a4, a5, a6, a7};
#pragma unroll
                    for (int i = 0; i < 8; i++) {
                        unsigned long long ad = dup2(av[i]);
                        fma2(acc[i][0], ad, b0.x);
                        fma2(acc[i][1], ad, b0.y);
                        fma2(acc[i][2], ad, b1.x);
                        fma2(acc[i][3], ad, b1.y);
                    }
                }
                BAR_XP();
            }

            // Store window results: 8 b rows x 8 cols (+bias) for timestep t_w.
            const int c0 = tn * 8;
            const int colbase = (c0 < 32) ? (jbase + c0) : (512 + jbase + (c0 - 32));
#pragma unroll
            for (int i = 0; i < 8; i++) {    // i = b within group
                float* dst = g_xp + ((size_t)t_w * BATCH + grp * BPG + i) * GATES
                           + colbase;
                float2 q0 = unpack2(acc[i][0]);
                float2 q1 = unpack2(acc[i][1]);
                float2 q2 = unpack2(acc[i][2]);
                float2 q3 = unpack2(acc[i][3]);
                float4 o0, o1;
                o0.x = q0.x + bv[0]; o0.y = q0.y + bv[1];
                o0.z = q1.x + bv[2]; o0.w = q1.y + bv[3];
                o1.x = q2.x + bv[4]; o1.y = q2.y + bv[5];
                o1.z = q3.x + bv[6]; o1.w = q3.y + bv[7];
                *(float4*)(dst)     = o0;
                *(float4*)(dst + 4) = o1;
            }
            BAR_XP();                        // all STGs of window W issued
            if (xid == 0)
                st_rel_cta_sh(flag_a, (unsigned)(W + 1));
        }
    }
}

extern "C" void kernel_launch(void* const* d_in, const int* in_sizes, int n_in,
                              void* d_out, int out_size) {
    const float* x    = (const float*)d_in[0];
    const float* wih  = (const float*)d_in[1];
    const float* whh  = (const float*)d_in[2];
    const float* bias = (const float*)d_in[3];
    float* out = (float*)d_out;

    const size_t smem_bytes = SM_FLOATS * sizeof(float);   // ~193 KB

    static int configured = 0;
    if (!configured) {
        cudaFuncSetAttribute(gru_fused,
                             cudaFuncAttributeMaxDynamicSharedMemorySize,
                             (int)smem_bytes);
        configured = 1;
    }

    gru_fused<<<NGROUP * GSIZE, THR, smem_bytes>>>(x, wih, whh, bias, out);
}